// round 4
// baseline (speedup 1.0000x reference)
#include <cuda_runtime.h>
#include <cuda_bf16.h>
#include <cstdint>

#define NN 524288   // nodes
#define DD 256      // input dim
#define HH 128      // hidden dim
#define BB 2048     // segments

// ---------------- scratch (device globals; no allocation allowed) ----------
__device__ float    g_scores[NN];
__device__ float    g_segmax[BB];
__device__ float    g_segsum[BB];
__device__ uint32_t g_w1p[DD * HH];   // permuted tf32 W1: [k][g*16 + a] = W1[k][a*8+g]

// ---------------- helpers ---------------------------------------------------
__device__ __forceinline__ uint32_t f2tf32(float f) {
    uint32_t u;
    asm("cvt.rna.tf32.f32 %0, %1;" : "=r"(u) : "f"(f));
    return u;
}

__device__ __forceinline__ void mma_tf32(float& c0, float& c1, float& c2, float& c3,
                                         uint32_t a0, uint32_t a1, uint32_t a2, uint32_t a3,
                                         uint32_t b0, uint32_t b1) {
    asm("mma.sync.aligned.m16n8k8.row.col.f32.tf32.tf32.f32 "
        "{%0,%1,%2,%3}, {%4,%5,%6,%7}, {%8,%9}, {%0,%1,%2,%3};"
        : "+f"(c0), "+f"(c1), "+f"(c2), "+f"(c3)
        : "r"(a0), "r"(a1), "r"(a2), "r"(a3), "r"(b0), "r"(b1));
}

// ---------------- kernel 0: permute + tf32-convert W1 (one-shot, tiny) -----
__global__ void w1perm_kernel(const float* __restrict__ W1) {
    int k = blockIdx.x;          // 0..255
    int c = threadIdx.x;         // 0..127
    g_w1p[k * HH + (c & 7) * 16 + (c >> 3)] = f2tf32(W1[k * HH + c]);
}

// ---------------- kernel A: scores = tanh(x@W1 + b1) @ W2 + b2 -------------
// 256 threads (8 warps), 2 CTAs/SM. CTA tile: 128 nodes x 128 cols.
// Warp tile: 16 nodes x 128 cols (16 m16n8k8 atoms).
// A (x) staged in smem row-major tf32, node stride 36 (conflict-free for
// STS.128 staging and scalar A loads: bank = 4g+t, all distinct).
// B (W1) read directly from g_w1p with LDG.128 (L1/L2 resident).
#define KC 32
#define XS_STRIDE 36
#define XBUF_U32 (128 * XS_STRIDE)          // 4608
#define SMEM_A_U32 (2 * XBUF_U32 + 256)
#define SMEM_A_BYTES (SMEM_A_U32 * 4)       // ~37.5 KB

__global__ void __launch_bounds__(256, 2)
scores_kernel(const float* __restrict__ x,
              const float* __restrict__ b1,
              const float* __restrict__ W2,
              const float* __restrict__ b2) {
    extern __shared__ uint32_t sm[];
    uint32_t* xs  = sm;                         // [2][128][36]
    float*    b1s = (float*)(sm + 2 * XBUF_U32);  // [128]
    float*    w2s = b1s + 128;                    // [128]

    const int tid  = threadIdx.x;
    const int lane = tid & 31;
    const int wid  = tid >> 5;
    const int t    = lane & 3;      // k row within group
    const int g    = lane >> 2;     // group id
    const int wn   = wid * 16;      // warp node base
    const int n0   = blockIdx.x * 128;

    if (tid < 128) { b1s[tid] = b1[tid]; w2s[tid] = W2[tid]; }

    float acc[16][4];
    #pragma unroll
    for (int a = 0; a < 16; ++a) {
        #pragma unroll
        for (int r = 0; r < 4; ++r) acc[a][r] = 0.0f;
    }

    const float4* x4 = (const float4*)x;

    // prefetch chunk 0: 1024 float4 per chunk, 4 per thread
    float4 rx[4];
    #pragma unroll
    for (int tt = 0; tt < 4; ++tt) {
        int id = tid + tt * 256;
        int node = id >> 3, q = id & 7;
        rx[tt] = x4[(size_t)(n0 + node) * 64 + q];
    }

    for (int ch = 0; ch < 8; ++ch) {
        uint32_t* xb = xs + (ch & 1) * XBUF_U32;

        // ---- store staged chunk (row-major, STS.128) ----
        #pragma unroll
        for (int tt = 0; tt < 4; ++tt) {
            int id = tid + tt * 256;
            int node = id >> 3, q = id & 7;
            uint4 u;
            u.x = f2tf32(rx[tt].x); u.y = f2tf32(rx[tt].y);
            u.z = f2tf32(rx[tt].z); u.w = f2tf32(rx[tt].w);
            *(uint4*)(xb + node * XS_STRIDE + 4 * q) = u;
        }
        __syncthreads();

        // ---- prefetch next chunk ----
        if (ch < 7) {
            #pragma unroll
            for (int tt = 0; tt < 4; ++tt) {
                int id = tid + tt * 256;
                int node = id >> 3, q = id & 7;
                rx[tt] = x4[(size_t)(n0 + node) * 64 + (ch + 1) * 8 + q];
            }
        }

        // ---- compute 4 k-steps ----
        #pragma unroll
        for (int ks = 0; ks < 4; ++ks) {
            int kl = ks * 8;
            // A fragments (scalar LDS, conflict-free)
            uint32_t a0 = xb[(wn + g)     * XS_STRIDE + kl + t];
            uint32_t a1 = xb[(wn + g + 8) * XS_STRIDE + kl + t];
            uint32_t a2 = xb[(wn + g)     * XS_STRIDE + kl + t + 4];
            uint32_t a3 = xb[(wn + g + 8) * XS_STRIDE + kl + t + 4];

            // B fragments straight from global (L1/L2 resident)
            const uint32_t* wr0 = g_w1p + (ch * KC + kl + t) * HH + g * 16;
            const uint32_t* wr1 = wr0 + 4 * HH;

            uint4 u0 = __ldg((const uint4*)(wr0));
            uint4 v0 = __ldg((const uint4*)(wr1));
            mma_tf32(acc[0][0], acc[0][1], acc[0][2], acc[0][3], a0, a1, a2, a3, u0.x, v0.x);
            mma_tf32(acc[1][0], acc[1][1], acc[1][2], acc[1][3], a0, a1, a2, a3, u0.y, v0.y);
            mma_tf32(acc[2][0], acc[2][1], acc[2][2], acc[2][3], a0, a1, a2, a3, u0.z, v0.z);
            mma_tf32(acc[3][0], acc[3][1], acc[3][2], acc[3][3], a0, a1, a2, a3, u0.w, v0.w);

            uint4 u1 = __ldg((const uint4*)(wr0 + 4));
            uint4 v1 = __ldg((const uint4*)(wr1 + 4));
            mma_tf32(acc[4][0], acc[4][1], acc[4][2], acc[4][3], a0, a1, a2, a3, u1.x, v1.x);
            mma_tf32(acc[5][0], acc[5][1], acc[5][2], acc[5][3], a0, a1, a2, a3, u1.y, v1.y);
            mma_tf32(acc[6][0], acc[6][1], acc[6][2], acc[6][3], a0, a1, a2, a3, u1.z, v1.z);
            mma_tf32(acc[7][0], acc[7][1], acc[7][2], acc[7][3], a0, a1, a2, a3, u1.w, v1.w);

            uint4 u2 = __ldg((const uint4*)(wr0 + 8));
            uint4 v2 = __ldg((const uint4*)(wr1 + 8));
            mma_tf32(acc[8][0],  acc[8][1],  acc[8][2],  acc[8][3],  a0, a1, a2, a3, u2.x, v2.x);
            mma_tf32(acc[9][0],  acc[9][1],  acc[9][2],  acc[9][3],  a0, a1, a2, a3, u2.y, v2.y);
            mma_tf32(acc[10][0], acc[10][1], acc[10][2], acc[10][3], a0, a1, a2, a3, u2.z, v2.z);
            mma_tf32(acc[11][0], acc[11][1], acc[11][2], acc[11][3], a0, a1, a2, a3, u2.w, v2.w);

            uint4 u3 = __ldg((const uint4*)(wr0 + 12));
            uint4 v3 = __ldg((const uint4*)(wr1 + 12));
            mma_tf32(acc[12][0], acc[12][1], acc[12][2], acc[12][3], a0, a1, a2, a3, u3.x, v3.x);
            mma_tf32(acc[13][0], acc[13][1], acc[13][2], acc[13][3], a0, a1, a2, a3, u3.y, v3.y);
            mma_tf32(acc[14][0], acc[14][1], acc[14][2], acc[14][3], a0, a1, a2, a3, u3.z, v3.z);
            mma_tf32(acc[15][0], acc[15][1], acc[15][2], acc[15][3], a0, a1, a2, a3, u3.w, v3.w);
        }
        __syncthreads();
    }

    // ---- epilogue: +b1, tanh, dot W2, reduce over t lanes ----
    float p0 = 0.0f, p1 = 0.0f;
    #pragma unroll
    for (int a = 0; a < 16; ++a) {
        #pragma unroll
        for (int rr = 0; rr < 2; ++rr) {
            int cc = a * 8 + 2 * t + rr;
            float bb = b1s[cc], ww = w2s[cc];
            p0 += tanhf(acc[a][rr]     + bb) * ww;   // node wn+g
            p1 += tanhf(acc[a][2 + rr] + bb) * ww;   // node wn+g+8
        }
    }
    p0 += __shfl_xor_sync(0xffffffffu, p0, 1);
    p0 += __shfl_xor_sync(0xffffffffu, p0, 2);
    p1 += __shfl_xor_sync(0xffffffffu, p1, 1);
    p1 += __shfl_xor_sync(0xffffffffu, p1, 2);
    if (t == 0) {
        float bb2 = b2[0];
        int node = n0 + wn + g;
        g_scores[node]     = p0 + bb2;
        g_scores[node + 8] = p1 + bb2;
    }
}

// ---------------- binary search: first i with batch[i] >= v ----------------
__device__ __forceinline__ int lower_bound_i32(const int* __restrict__ a, int n, int v) {
    int lo = 0, hi = n;
    while (lo < hi) {
        int mid = (lo + hi) >> 1;
        if (a[mid] < v) lo = mid + 1; else hi = mid;
    }
    return lo;
}

// ---------------- kernel B: per-segment max + sum(exp) ---------------------
__global__ void segstats_kernel(const int* __restrict__ batch) {
    const int b = blockIdx.x;
    const int tid = threadIdx.x;
    __shared__ int se[2];
    __shared__ float red[256];

    if (tid == 0) {
        se[0] = lower_bound_i32(batch, NN, b);
        se[1] = lower_bound_i32(batch, NN, b + 1);
    }
    __syncthreads();
    const int st = se[0], en = se[1];

    float m = -1e30f;
    for (int i = st + tid; i < en; i += 256) m = fmaxf(m, g_scores[i]);
    red[tid] = m;
    __syncthreads();
    #pragma unroll
    for (int off = 128; off > 0; off >>= 1) {
        if (tid < off) red[tid] = fmaxf(red[tid], red[tid + off]);
        __syncthreads();
    }
    m = red[0];
    __syncthreads();

    float z = 0.0f;
    for (int i = st + tid; i < en; i += 256) z += expf(g_scores[i] - m);
    red[tid] = z;
    __syncthreads();
    #pragma unroll
    for (int off = 128; off > 0; off >>= 1) {
        if (tid < off) red[tid] += red[tid + off];
        __syncthreads();
    }
    if (tid == 0) {
        if (en > st) { g_segmax[b] = m; g_segsum[b] = red[0]; }
        else         { g_segmax[b] = 0.0f; g_segsum[b] = 0.0f; }
    }
}

// ---------------- kernel C: pooled[b,d] = sum_i x[i,d] * w_i ----------------
__global__ void pool_kernel(const float* __restrict__ x,
                            const int* __restrict__ batch,
                            float* __restrict__ out) {
    const int b = blockIdx.x;
    const int tid = threadIdx.x;   // = dim d (0..255)
    __shared__ int se[2];
    __shared__ float ws[256];

    if (tid == 0) {
        se[0] = lower_bound_i32(batch, NN, b);
        se[1] = lower_bound_i32(batch, NN, b + 1);
    }
    __syncthreads();
    const int st = se[0], en = se[1];
    const float m = g_segmax[b];
    const float Z = g_segsum[b];
    const float invZ = (en > st && Z > 0.0f) ? (1.0f / Z) : 0.0f;

    float acc = 0.0f;
    for (int i0 = st; i0 < en; i0 += 256) {
        int cnt = min(256, en - i0);
        __syncthreads();
        if (tid < cnt) ws[tid] = expf(g_scores[i0 + tid] - m) * invZ;
        __syncthreads();
        const float* xp = x + (size_t)i0 * DD + tid;
        int j = 0;
        for (; j + 8 <= cnt; j += 8) {
            float v0 = xp[(size_t)(j + 0) * DD];
            float v1 = xp[(size_t)(j + 1) * DD];
            float v2 = xp[(size_t)(j + 2) * DD];
            float v3 = xp[(size_t)(j + 3) * DD];
            float v4 = xp[(size_t)(j + 4) * DD];
            float v5 = xp[(size_t)(j + 5) * DD];
            float v6 = xp[(size_t)(j + 6) * DD];
            float v7 = xp[(size_t)(j + 7) * DD];
            acc += v0 * ws[j + 0]; acc += v1 * ws[j + 1];
            acc += v2 * ws[j + 2]; acc += v3 * ws[j + 3];
            acc += v4 * ws[j + 4]; acc += v5 * ws[j + 5];
            acc += v6 * ws[j + 6]; acc += v7 * ws[j + 7];
        }
        for (; j < cnt; ++j) acc += xp[(size_t)j * DD] * ws[j];
    }
    out[(size_t)b * DD + tid] = acc;
}

// ---------------- launch -----------------------------------------------------
extern "C" void kernel_launch(void* const* d_in, const int* in_sizes, int n_in,
                              void* d_out, int out_size) {
    (void)in_sizes; (void)n_in; (void)out_size;
    const float* x     = (const float*)d_in[0];
    const int*   batch = (const int*)d_in[1];
    const float* W1    = (const float*)d_in[2];
    const float* b1    = (const float*)d_in[3];
    const float* W2    = (const float*)d_in[4];
    const float* b2    = (const float*)d_in[5];
    float*       out   = (float*)d_out;

    cudaFuncSetAttribute(scores_kernel,
                         cudaFuncAttributeMaxDynamicSharedMemorySize,
                         SMEM_A_BYTES);

    w1perm_kernel<<<DD, HH>>>(W1);
    scores_kernel<<<NN / 128, 256, SMEM_A_BYTES>>>(x, b1, W2, b2);
    segstats_kernel<<<BB, 256>>>(batch);
    pool_kernel<<<BB, 256>>>(x, batch, out);
}

// round 5
// speedup vs baseline: 1.8299x; 1.8299x over previous
#include <cuda_runtime.h>
#include <cuda_bf16.h>
#include <cstdint>

#define NN 524288   // nodes
#define DD 256      // input dim
#define HH 128      // hidden dim
#define BB 2048     // segments

// ---------------- scratch (device globals; no allocation allowed) ----------
__device__ float    g_scores[NN];
__device__ float    g_segmax[BB];
__device__ float    g_segsum[BB];
__device__ uint32_t g_w1p[DD * HH];   // permuted tf32 W1: [k][(c&7)*16 + (c>>3)]

// ---------------- helpers ---------------------------------------------------
__device__ __forceinline__ uint32_t f2tf32(float f) {
    uint32_t u;
    asm("cvt.rna.tf32.f32 %0, %1;" : "=r"(u) : "f"(f));
    return u;
}

__device__ __forceinline__ void mma_tf32(float& c0, float& c1, float& c2, float& c3,
                                         uint32_t a0, uint32_t a1, uint32_t a2, uint32_t a3,
                                         uint32_t b0, uint32_t b1) {
    asm("mma.sync.aligned.m16n8k8.row.col.f32.tf32.tf32.f32 "
        "{%0,%1,%2,%3}, {%4,%5,%6,%7}, {%8,%9}, {%0,%1,%2,%3};"
        : "+f"(c0), "+f"(c1), "+f"(c2), "+f"(c3)
        : "r"(a0), "r"(a1), "r"(a2), "r"(a3), "r"(b0), "r"(b1));
}

// ---------------- kernel 0: permute + tf32-convert W1 (one-shot, tiny) -----
// Column c = a*8 + gg maps to position gg*16 + a. B-frag for thread group gg,
// atoms a..a+3 is then a single LDS.128.
__global__ void w1perm_kernel(const float* __restrict__ W1) {
    int k = blockIdx.x;          // 0..255
    int c = threadIdx.x;         // 0..127
    g_w1p[k * HH + (c & 7) * 16 + (c >> 3)] = f2tf32(W1[k * HH + c]);
}

// ---------------- kernel A: scores = tanh(x@W1 + b1) @ W2 + b2 -------------
// 256 threads (8 warps), 2 CTAs/SM. CTA tile: 128 nodes x 128 cols.
// Warp tile: 16 nodes x 128 cols (16 m16n8k8 atoms).
// x chunk in smem row-major tf32, node stride 36 (conflict-free STS.128 &
// scalar A-LDS).  W1 chunk copied pre-permuted from g_w1p, row stride 132
// (== 4 mod 32 -> conflict-free LDS.128 B-frags). Both double-buffered.
#define KC 32
#define XS_STRIDE 36
#define W1P_STRIDE 132
#define XBUF_U32  (128 * XS_STRIDE)          // 4608
#define W1BUF_U32 (KC * W1P_STRIDE)          // 4224
#define SMEM_A_U32 (2 * XBUF_U32 + 2 * W1BUF_U32 + 256)
#define SMEM_A_BYTES (SMEM_A_U32 * 4)        // ~71.7 KB

__global__ void __launch_bounds__(256, 2)
scores_kernel(const float* __restrict__ x,
              const float* __restrict__ b1,
              const float* __restrict__ W2,
              const float* __restrict__ b2) {
    extern __shared__ uint32_t sm[];
    uint32_t* xs  = sm;                                  // [2][128][36]
    uint32_t* w1s = sm + 2 * XBUF_U32;                   // [2][32][132]
    float*    b1s = (float*)(sm + 2 * XBUF_U32 + 2 * W1BUF_U32);  // [128]
    float*    w2s = b1s + 128;                                     // [128]

    const int tid  = threadIdx.x;
    const int lane = tid & 31;
    const int wid  = tid >> 5;
    const int t    = lane & 3;      // k row within group
    const int g    = lane >> 2;     // group id
    const int wn   = wid * 16;      // warp node base
    const int n0   = blockIdx.x * 128;

    if (tid < 128) { b1s[tid] = b1[tid]; w2s[tid] = W2[tid]; }

    float acc[16][4];
    #pragma unroll
    for (int a = 0; a < 16; ++a) {
        #pragma unroll
        for (int r = 0; r < 4; ++r) acc[a][r] = 0.0f;
    }

    const float4* x4  = (const float4*)x;
    const uint4*  w4  = (const uint4*)g_w1p;

    // staging decompositions (constant per thread)
    const int xnode = tid >> 3, xq = tid & 7;        // +tt*32 nodes
    const int wkl   = tid >> 5, wwq = tid & 31;      // +tt*8 k-rows

    // ---- prefetch chunk 0 ----
    float4 rx[4];
    uint4  rw[4];
    #pragma unroll
    for (int tt = 0; tt < 4; ++tt) {
        rx[tt] = x4[(size_t)(n0 + xnode + tt * 32) * 64 + xq];
        rw[tt] = w4[(size_t)(wkl + tt * 8) * 32 + wwq];
    }

    for (int ch = 0; ch < 8; ++ch) {
        uint32_t* xb  = xs  + (ch & 1) * XBUF_U32;
        uint32_t* w1b = w1s + (ch & 1) * W1BUF_U32;

        // ---- store staged chunk (pure vector stores) ----
        #pragma unroll
        for (int tt = 0; tt < 4; ++tt) {
            uint4 u;
            u.x = f2tf32(rx[tt].x); u.y = f2tf32(rx[tt].y);
            u.z = f2tf32(rx[tt].z); u.w = f2tf32(rx[tt].w);
            *(uint4*)(xb + (xnode + tt * 32) * XS_STRIDE + 4 * xq) = u;
            *(uint4*)(w1b + (wkl + tt * 8) * W1P_STRIDE + 4 * wwq) = rw[tt];
        }
        __syncthreads();

        // ---- prefetch next chunk ----
        if (ch < 7) {
            #pragma unroll
            for (int tt = 0; tt < 4; ++tt) {
                rx[tt] = x4[(size_t)(n0 + xnode + tt * 32) * 64 + (ch + 1) * 8 + xq];
                rw[tt] = w4[(size_t)((ch + 1) * KC + wkl + tt * 8) * 32 + wwq];
            }
        }

        // ---- compute 4 k-steps ----
        #pragma unroll
        for (int ks = 0; ks < 4; ++ks) {
            int kl = ks * 8;
            uint32_t a0 = xb[(wn + g)     * XS_STRIDE + kl + t];
            uint32_t a1 = xb[(wn + g + 8) * XS_STRIDE + kl + t];
            uint32_t a2 = xb[(wn + g)     * XS_STRIDE + kl + t + 4];
            uint32_t a3 = xb[(wn + g + 8) * XS_STRIDE + kl + t + 4];

            const uint32_t* r0 = w1b + (kl + t) * W1P_STRIDE + g * 16;
            const uint32_t* r1 = r0 + 4 * W1P_STRIDE;

            uint4 u0 = *(const uint4*)(r0);
            uint4 v0 = *(const uint4*)(r1);
            mma_tf32(acc[0][0], acc[0][1], acc[0][2], acc[0][3], a0, a1, a2, a3, u0.x, v0.x);
            mma_tf32(acc[1][0], acc[1][1], acc[1][2], acc[1][3], a0, a1, a2, a3, u0.y, v0.y);
            mma_tf32(acc[2][0], acc[2][1], acc[2][2], acc[2][3], a0, a1, a2, a3, u0.z, v0.z);
            mma_tf32(acc[3][0], acc[3][1], acc[3][2], acc[3][3], a0, a1, a2, a3, u0.w, v0.w);

            uint4 u1 = *(const uint4*)(r0 + 4);
            uint4 v1 = *(const uint4*)(r1 + 4);
            mma_tf32(acc[4][0], acc[4][1], acc[4][2], acc[4][3], a0, a1, a2, a3, u1.x, v1.x);
            mma_tf32(acc[5][0], acc[5][1], acc[5][2], acc[5][3], a0, a1, a2, a3, u1.y, v1.y);
            mma_tf32(acc[6][0], acc[6][1], acc[6][2], acc[6][3], a0, a1, a2, a3, u1.z, v1.z);
            mma_tf32(acc[7][0], acc[7][1], acc[7][2], acc[7][3], a0, a1, a2, a3, u1.w, v1.w);

            uint4 u2 = *(const uint4*)(r0 + 8);
            uint4 v2 = *(const uint4*)(r1 + 8);
            mma_tf32(acc[8][0],  acc[8][1],  acc[8][2],  acc[8][3],  a0, a1, a2, a3, u2.x, v2.x);
            mma_tf32(acc[9][0],  acc[9][1],  acc[9][2],  acc[9][3],  a0, a1, a2, a3, u2.y, v2.y);
            mma_tf32(acc[10][0], acc[10][1], acc[10][2], acc[10][3], a0, a1, a2, a3, u2.z, v2.z);
            mma_tf32(acc[11][0], acc[11][1], acc[11][2], acc[11][3], a0, a1, a2, a3, u2.w, v2.w);

            uint4 u3 = *(const uint4*)(r0 + 12);
            uint4 v3 = *(const uint4*)(r1 + 12);
            mma_tf32(acc[12][0], acc[12][1], acc[12][2], acc[12][3], a0, a1, a2, a3, u3.x, v3.x);
            mma_tf32(acc[13][0], acc[13][1], acc[13][2], acc[13][3], a0, a1, a2, a3, u3.y, v3.y);
            mma_tf32(acc[14][0], acc[14][1], acc[14][2], acc[14][3], a0, a1, a2, a3, u3.z, v3.z);
            mma_tf32(acc[15][0], acc[15][1], acc[15][2], acc[15][3], a0, a1, a2, a3, u3.w, v3.w);
        }
        __syncthreads();
    }

    // ---- epilogue: +b1, tanh, dot W2, reduce over t lanes ----
    float p0 = 0.0f, p1 = 0.0f;
    #pragma unroll
    for (int a = 0; a < 16; ++a) {
        #pragma unroll
        for (int rr = 0; rr < 2; ++rr) {
            int cc = a * 8 + 2 * t + rr;
            float bb = b1s[cc], ww = w2s[cc];
            p0 += tanhf(acc[a][rr]     + bb) * ww;   // node wn+g
            p1 += tanhf(acc[a][2 + rr] + bb) * ww;   // node wn+g+8
        }
    }
    p0 += __shfl_xor_sync(0xffffffffu, p0, 1);
    p0 += __shfl_xor_sync(0xffffffffu, p0, 2);
    p1 += __shfl_xor_sync(0xffffffffu, p1, 1);
    p1 += __shfl_xor_sync(0xffffffffu, p1, 2);
    if (t == 0) {
        float bb2 = b2[0];
        int node = n0 + wn + g;
        g_scores[node]     = p0 + bb2;
        g_scores[node + 8] = p1 + bb2;
    }
}

// ---------------- binary search: first i with batch[i] >= v ----------------
__device__ __forceinline__ int lower_bound_i32(const int* __restrict__ a, int n, int v) {
    int lo = 0, hi = n;
    while (lo < hi) {
        int mid = (lo + hi) >> 1;
        if (a[mid] < v) lo = mid + 1; else hi = mid;
    }
    return lo;
}

// ---------------- kernel B: per-segment max + sum(exp) ---------------------
__global__ void segstats_kernel(const int* __restrict__ batch) {
    const int b = blockIdx.x;
    const int tid = threadIdx.x;
    __shared__ int se[2];
    __shared__ float red[256];

    if (tid == 0) {
        se[0] = lower_bound_i32(batch, NN, b);
        se[1] = lower_bound_i32(batch, NN, b + 1);
    }
    __syncthreads();
    const int st = se[0], en = se[1];

    float m = -1e30f;
    for (int i = st + tid; i < en; i += 256) m = fmaxf(m, g_scores[i]);
    red[tid] = m;
    __syncthreads();
    #pragma unroll
    for (int off = 128; off > 0; off >>= 1) {
        if (tid < off) red[tid] = fmaxf(red[tid], red[tid + off]);
        __syncthreads();
    }
    m = red[0];
    __syncthreads();

    float z = 0.0f;
    for (int i = st + tid; i < en; i += 256) z += expf(g_scores[i] - m);
    red[tid] = z;
    __syncthreads();
    #pragma unroll
    for (int off = 128; off > 0; off >>= 1) {
        if (tid < off) red[tid] += red[tid + off];
        __syncthreads();
    }
    if (tid == 0) {
        if (en > st) { g_segmax[b] = m; g_segsum[b] = red[0]; }
        else         { g_segmax[b] = 0.0f; g_segsum[b] = 0.0f; }
    }
}

// ---------------- kernel C: pooled[b,d] = sum_i x[i,d] * w_i ----------------
__global__ void pool_kernel(const float* __restrict__ x,
                            const int* __restrict__ batch,
                            float* __restrict__ out) {
    const int b = blockIdx.x;
    const int tid = threadIdx.x;   // = dim d (0..255)
    __shared__ int se[2];
    __shared__ float ws[256];

    if (tid == 0) {
        se[0] = lower_bound_i32(batch, NN, b);
        se[1] = lower_bound_i32(batch, NN, b + 1);
    }
    __syncthreads();
    const int st = se[0], en = se[1];
    const float m = g_segmax[b];
    const float Z = g_segsum[b];
    const float invZ = (en > st && Z > 0.0f) ? (1.0f / Z) : 0.0f;

    float acc = 0.0f;
    for (int i0 = st; i0 < en; i0 += 256) {
        int cnt = min(256, en - i0);
        __syncthreads();
        if (tid < cnt) ws[tid] = expf(g_scores[i0 + tid] - m) * invZ;
        __syncthreads();
        const float* xp = x + (size_t)i0 * DD + tid;
        int j = 0;
        for (; j + 8 <= cnt; j += 8) {
            float v0 = xp[(size_t)(j + 0) * DD];
            float v1 = xp[(size_t)(j + 1) * DD];
            float v2 = xp[(size_t)(j + 2) * DD];
            float v3 = xp[(size_t)(j + 3) * DD];
            float v4 = xp[(size_t)(j + 4) * DD];
            float v5 = xp[(size_t)(j + 5) * DD];
            float v6 = xp[(size_t)(j + 6) * DD];
            float v7 = xp[(size_t)(j + 7) * DD];
            acc += v0 * ws[j + 0]; acc += v1 * ws[j + 1];
            acc += v2 * ws[j + 2]; acc += v3 * ws[j + 3];
            acc += v4 * ws[j + 4]; acc += v5 * ws[j + 5];
            acc += v6 * ws[j + 6]; acc += v7 * ws[j + 7];
        }
        for (; j < cnt; ++j) acc += xp[(size_t)j * DD] * ws[j];
    }
    out[(size_t)b * DD + tid] = acc;
}

// ---------------- launch -----------------------------------------------------
extern "C" void kernel_launch(void* const* d_in, const int* in_sizes, int n_in,
                              void* d_out, int out_size) {
    (void)in_sizes; (void)n_in; (void)out_size;
    const float* x     = (const float*)d_in[0];
    const int*   batch = (const int*)d_in[1];
    const float* W1    = (const float*)d_in[2];
    const float* b1    = (const float*)d_in[3];
    const float* W2    = (const float*)d_in[4];
    const float* b2    = (const float*)d_in[5];
    float*       out   = (float*)d_out;

    cudaFuncSetAttribute(scores_kernel,
                         cudaFuncAttributeMaxDynamicSharedMemorySize,
                         SMEM_A_BYTES);

    w1perm_kernel<<<DD, HH>>>(W1);
    scores_kernel<<<NN / 128, 256, SMEM_A_BYTES>>>(x, b1, W2, b2);
    segstats_kernel<<<BB, 256>>>(batch);
    pool_kernel<<<BB, 256>>>(x, batch, out);
}

// round 7
// speedup vs baseline: 2.0689x; 1.1306x over previous
#include <cuda_runtime.h>
#include <cstdint>

#define NN 524288   // nodes
#define DD 256      // input dim
#define HH 128      // hidden dim
#define BB 2048     // segments

// ---------------- scratch (device globals; no allocation allowed) ----------
__device__ float    g_scores[NN];
__device__ float    g_segmax[BB];
__device__ float    g_segsum[BB];
__device__ uint32_t g_w1p[DD * HH];   // permuted tf32 W1: [k][(c&7)*16 + (c>>3)]

// ---------------- helpers ---------------------------------------------------
__device__ __forceinline__ uint32_t f2tf32(float f) {
    uint32_t u;
    asm("cvt.rna.tf32.f32 %0, %1;" : "=r"(u) : "f"(f));
    return u;
}
__device__ __forceinline__ float tanha(float x) {
    float y;
    asm("tanh.approx.f32 %0, %1;" : "=f"(y) : "f"(x));
    return y;
}
__device__ __forceinline__ uint32_t smem_u32(const void* p) {
    uint32_t a;
    asm("{ .reg .u64 t; cvta.to.shared.u64 t, %1; cvt.u32.u64 %0, t; }" : "=r"(a) : "l"(p));
    return a;
}
#define CP16(dst, src)  asm volatile("cp.async.ca.shared.global [%0], [%1], 16;" :: "r"(dst), "l"(src) : "memory")
#define CP_COMMIT()     asm volatile("cp.async.commit_group;" ::: "memory")
#define CP_WAIT(n)      asm volatile("cp.async.wait_group %0;" :: "n"(n) : "memory")

__device__ __forceinline__ void mma_tf32(float& c0, float& c1, float& c2, float& c3,
                                         uint32_t a0, uint32_t a1, uint32_t a2, uint32_t a3,
                                         uint32_t b0, uint32_t b1) {
    asm("mma.sync.aligned.m16n8k8.row.col.f32.tf32.tf32.f32 "
        "{%0,%1,%2,%3}, {%4,%5,%6,%7}, {%8,%9}, {%0,%1,%2,%3};"
        : "+f"(c0), "+f"(c1), "+f"(c2), "+f"(c3)
        : "r"(a0), "r"(a1), "r"(a2), "r"(a3), "r"(b0), "r"(b1));
}

// ---------------- kernel 0: permute + tf32-convert W1 (one-shot, tiny) -----
__global__ void w1perm_kernel(const float* __restrict__ W1) {
    int k = blockIdx.x;          // 0..255
    int c = threadIdx.x;         // 0..127
    g_w1p[k * HH + (c & 7) * 16 + (c >> 3)] = f2tf32(W1[k * HH + c]);
}

// ---------------- kernel A: scores = tanh(x@W1 + b1) @ W2 + b2 -------------
// 256 threads (8 warps), 2 CTAs/SM. CTA tile: 128 nodes x 128 cols.
// Warp tile: 32 nodes x 64 cols (2 row-atoms x 8 col-atoms).
//   wid&3  = node slice (32 nodes), wid>>2 = column half.
// x chunk in smem row-major tf32, node stride 36 (register prefetch + STS.128).
// W1 chunk staged from pre-permuted g_w1p via cp.async (no regs, no STS),
// row stride 132 (conflict-free LDS.128 B-frags). Both double-buffered.
#define KC 32
#define XS_STRIDE  36
#define W1P_STRIDE 132
#define XBUF_B  (128 * XS_STRIDE * 4)   // 18432 B
#define W1BUF_B (KC * W1P_STRIDE * 4)   // 16896 B
#define OFF_X   0
#define OFF_W1  (2 * XBUF_B)            // 36864
#define OFF_B1  (OFF_W1 + 2 * W1BUF_B)  // 70656
#define OFF_W2  (OFF_B1 + 512)
#define OFF_PART (OFF_W2 + 512)
#define OFF_B2  (OFF_PART + 512)
#define SMEM_A_BYTES (OFF_B2 + 16)      // ~72.2 KB

__global__ void __launch_bounds__(256, 2)
scores_kernel(const float* __restrict__ x,
              const float* __restrict__ b1,
              const float* __restrict__ W2,
              const float* __restrict__ b2) {
    extern __shared__ char smem[];
    const uint32_t sb = smem_u32(smem);

    float* b1s  = (float*)(smem + OFF_B1);
    float* w2s  = (float*)(smem + OFF_W2);
    float* part = (float*)(smem + OFF_PART);

    const int tid  = threadIdx.x;
    const int lane = tid & 31;
    const int wid  = tid >> 5;
    const int t    = lane & 3;      // k row within group
    const int g    = lane >> 2;     // group id
    const int wn   = (wid & 3) * 32;   // warp node base (32-node slice)
    const int chf  = wid >> 2;         // column half
    const int n0   = blockIdx.x * 128;

    if (tid < 128) { b1s[tid] = b1[tid]; w2s[tid] = W2[tid]; }
    if (tid == 0)  { ((float*)(smem + OFF_B2))[0] = b2[0]; }

    float acc[2][8][4];
    #pragma unroll
    for (int ra = 0; ra < 2; ++ra)
        #pragma unroll
        for (int j = 0; j < 8; ++j)
            #pragma unroll
            for (int r = 0; r < 4; ++r) acc[ra][j][r] = 0.0f;

    const float4* x4 = (const float4*)x;
    const char*   wsrc = (const char*)g_w1p;

    // per-thread staging decompositions
    const int xnode = tid >> 3, xq = tid & 7;   // +i*32 nodes, 16B group xq
    const int wrow  = tid >> 5, wq = tid & 31;  // +tt*8 k-rows, 16B group wq

    // ---- prologue: cp.async W1 chunk 0 into buf 0; prefetch x chunk 0 ----
    #pragma unroll
    for (int tt = 0; tt < 4; ++tt) {
        int row = wrow + tt * 8;
        CP16(sb + OFF_W1 + (uint32_t)(row * W1P_STRIDE + 4 * wq) * 4,
             wsrc + (size_t)(row * 128 + 4 * wq) * 4);
    }
    CP_COMMIT();

    float4 rx[4];
    #pragma unroll
    for (int i = 0; i < 4; ++i) {
        rx[i] = x4[(size_t)(n0 + xnode + i * 32) * 64 + xq];
    }

    for (int ch = 0; ch < 8; ++ch) {
        const int buf = ch & 1;
        uint32_t* xb  = (uint32_t*)(smem + OFF_X  + buf * XBUF_B);
        uint32_t* w1b = (uint32_t*)(smem + OFF_W1 + buf * W1BUF_B);

        // ---- store staged x chunk (rna tf32, STS.128) ----
        #pragma unroll
        for (int i = 0; i < 4; ++i) {
            uint4 u;
            u.x = f2tf32(rx[i].x); u.y = f2tf32(rx[i].y);
            u.z = f2tf32(rx[i].z); u.w = f2tf32(rx[i].w);
            *(uint4*)(xb + (xnode + i * 32) * XS_STRIDE + 4 * xq) = u;
        }

        // ---- issue next chunk's loads ----
        if (ch < 7) {
            #pragma unroll
            for (int tt = 0; tt < 4; ++tt) {
                int row = wrow + tt * 8;
                CP16(sb + OFF_W1 + (uint32_t)((buf ^ 1) * W1BUF_B) +
                         (uint32_t)(row * W1P_STRIDE + 4 * wq) * 4,
                     wsrc + (size_t)(((ch + 1) * KC + row) * 128 + 4 * wq) * 4);
            }
            CP_COMMIT();
            #pragma unroll
            for (int i = 0; i < 4; ++i) {
                rx[i] = x4[(size_t)(n0 + xnode + i * 32) * 64 + (ch + 1) * 8 + xq];
            }
            CP_WAIT(1);   // chunk ch's W1 group complete; ch+1 may stay in flight
        } else {
            CP_WAIT(0);
        }
        __syncthreads();

        // ---- compute 4 k-steps ----
        #pragma unroll
        for (int ks = 0; ks < 4; ++ks) {
            const int kl = ks * 8;
            // A fragments: 4 node rows x 2 k positions (scalar LDS, conflict-free)
            uint32_t ax[4][2];
            #pragma unroll
            for (int m = 0; m < 4; ++m) {
                ax[m][0] = xb[(wn + g + 8 * m) * XS_STRIDE + kl + t];
                ax[m][1] = xb[(wn + g + 8 * m) * XS_STRIDE + kl + t + 4];
            }
            // B fragments: 8 col-atoms, 2 k positions (LDS.128, conflict-free)
            const uint32_t* r0 = w1b + (kl + t) * W1P_STRIDE + g * 16 + chf * 8;
            const uint32_t* r1 = r0 + 4 * W1P_STRIDE;
            uint4 u0 = *(const uint4*)(r0);
            uint4 u1 = *(const uint4*)(r0 + 4);
            uint4 v0 = *(const uint4*)(r1);
            uint4 v1 = *(const uint4*)(r1 + 4);
            uint32_t bu[8] = {u0.x, u0.y, u0.z, u0.w, u1.x, u1.y, u1.z, u1.w};
            uint32_t bv[8] = {v0.x, v0.y, v0.z, v0.w, v1.x, v1.y, v1.z, v1.w};

            #pragma unroll
            for (int ra = 0; ra < 2; ++ra) {
                uint32_t a0 = ax[2 * ra][0],     a1 = ax[2 * ra + 1][0];
                uint32_t a2 = ax[2 * ra][1],     a3 = ax[2 * ra + 1][1];
                #pragma unroll
                for (int j = 0; j < 8; ++j) {
                    mma_tf32(acc[ra][j][0], acc[ra][j][1], acc[ra][j][2], acc[ra][j][3],
                             a0, a1, a2, a3, bu[j], bv[j]);
                }
            }
        }
        __syncthreads();
    }

    // ---- epilogue: +b1, tanh, dot W2, reduce over t, combine col halves ----
    // p[0]: node wn+g      p[1]: node wn+g+8
    // p[2]: node wn+g+16   p[3]: node wn+g+24
    float p[4] = {0.f, 0.f, 0.f, 0.f};
    #pragma unroll
    for (int ra = 0; ra < 2; ++ra) {
        #pragma unroll
        for (int j = 0; j < 8; ++j) {
            #pragma unroll
            for (int rr = 0; rr < 2; ++rr) {
                int cc = (chf * 8 + j) * 8 + 2 * t + rr;
                float bb = b1s[cc], ww = w2s[cc];
                p[2 * ra]     += tanha(acc[ra][j][rr]     + bb) * ww;
                p[2 * ra + 1] += tanha(acc[ra][j][2 + rr] + bb) * ww;
            }
        }
    }
    #pragma unroll
    for (int i = 0; i < 4; ++i) {
        p[i] += __shfl_xor_sync(0xffffffffu, p[i], 1);
        p[i] += __shfl_xor_sync(0xffffffffu, p[i], 2);
    }
    if (t == 0 && chf == 0) {
        part[wn + g]      = p[0];
        part[wn + g + 8]  = p[1];
        part[wn + g + 16] = p[2];
        part[wn + g + 24] = p[3];
    }
    __syncthreads();
    if (t == 0 && chf == 1) {
        float bb2 = ((float*)(smem + OFF_B2))[0];
        g_scores[n0 + wn + g]      = part[wn + g]      + p[0] + bb2;
        g_scores[n0 + wn + g + 8]  = part[wn + g + 8]  + p[1] + bb2;
        g_scores[n0 + wn + g + 16] = part[wn + g + 16] + p[2] + bb2;
        g_scores[n0 + wn + g + 24] = part[wn + g + 24] + p[3] + bb2;
    }
}

// ---------------- binary search ---------------------------------------------
__device__ __forceinline__ int lower_bound_i32(const int* __restrict__ a, int n, int v) {
    int lo = 0, hi = n;
    while (lo < hi) {
        int mid = (lo + hi) >> 1;
        if (a[mid] < v) lo = mid + 1; else hi = mid;
    }
    return lo;
}

// ---------------- kernel B: per-segment max + sum(exp) ----------------------
__global__ void segstats_kernel(const int* __restrict__ batch) {
    const int b = blockIdx.x;
    const int tid = threadIdx.x;
    __shared__ int se[2];
    __shared__ float red[256];

    if (tid == 0) {
        se[0] = lower_bound_i32(batch, NN, b);
        se[1] = lower_bound_i32(batch, NN, b + 1);
    }
    __syncthreads();
    const int st = se[0], en = se[1];

    float m = -1e30f;
    for (int i = st + tid; i < en; i += 256) m = fmaxf(m, g_scores[i]);
    red[tid] = m;
    __syncthreads();
    #pragma unroll
    for (int off = 128; off > 0; off >>= 1) {
        if (tid < off) red[tid] = fmaxf(red[tid], red[tid + off]);
        __syncthreads();
    }
    m = red[0];
    __syncthreads();

    float z = 0.0f;
    for (int i = st + tid; i < en; i += 256) z += expf(g_scores[i] - m);
    red[tid] = z;
    __syncthreads();
    #pragma unroll
    for (int off = 128; off > 0; off >>= 1) {
        if (tid < off) red[tid] += red[tid + off];
        __syncthreads();
    }
    if (tid == 0) {
        if (en > st) { g_segmax[b] = m; g_segsum[b] = red[0]; }
        else         { g_segmax[b] = 0.0f; g_segsum[b] = 0.0f; }
    }
}

// ---------------- kernel C: weighted pooling (float4 loads) ------------------
// 256 threads: thread owns dims [4*(t&63), +4) for node group (t>>6);
// node j handled by group j&3. Cross-group reduce via smem.
__global__ void pool_kernel(const float* __restrict__ x,
                            const int* __restrict__ batch,
                            float* __restrict__ out) {
    const int b = blockIdx.x;
    const int tid = threadIdx.x;
    const int dgrp = tid & 63;
    const int ng   = tid >> 6;
    __shared__ int se[2];
    __shared__ float ws[256];
    __shared__ float4 sred[4 * 64];

    if (tid == 0) {
        se[0] = lower_bound_i32(batch, NN, b);
        se[1] = lower_bound_i32(batch, NN, b + 1);
    }
    __syncthreads();
    const int st = se[0], en = se[1];
    const float m = g_segmax[b];
    const float Z = g_segsum[b];
    const float invZ = (en > st && Z > 0.0f) ? (1.0f / Z) : 0.0f;

    const float4* x4 = (const float4*)x;
    float4 a = make_float4(0.f, 0.f, 0.f, 0.f);

    for (int i0 = st; i0 < en; i0 += 256) {
        int cnt = min(256, en - i0);
        __syncthreads();
        if (tid < cnt) ws[tid] = expf(g_scores[i0 + tid] - m) * invZ;
        __syncthreads();
        for (int j = ng; j < cnt; j += 4) {
            float w = ws[j];
            float4 v = x4[(size_t)(i0 + j) * 64 + dgrp];
            a.x += v.x * w; a.y += v.y * w; a.z += v.z * w; a.w += v.w * w;
        }
    }
    sred[ng * 64 + dgrp] = a;
    __syncthreads();
    const float* sf = (const float*)sred;
    float r = sf[tid] + sf[256 + tid] + sf[512 + tid] + sf[768 + tid];
    out[(size_t)b * DD + tid] = r;
}

// ---------------- launch ------------------------------------------------------
extern "C" void kernel_launch(void* const* d_in, const int* in_sizes, int n_in,
                              void* d_out, int out_size) {
    (void)in_sizes; (void)n_in; (void)out_size;
    const float* x     = (const float*)d_in[0];
    const int*   batch = (const int*)d_in[1];
    const float* W1    = (const float*)d_in[2];
    const float* b1    = (const float*)d_in[3];
    const float* W2    = (const float*)d_in[4];
    const float* b2    = (const float*)d_in[5];
    float*       out   = (float*)d_out;

    cudaFuncSetAttribute(scores_kernel,
                         cudaFuncAttributeMaxDynamicSharedMemorySize,
                         SMEM_A_BYTES);

    w1perm_kernel<<<DD, HH>>>(W1);
    scores_kernel<<<NN / 128, 256, SMEM_A_BYTES>>>(x, b1, W2, b2);
    segstats_kernel<<<BB, 256>>>(batch);
    pool_kernel<<<BB, 256>>>(x, batch, out);
}

// round 8
// speedup vs baseline: 2.0800x; 1.0054x over previous
#include <cuda_runtime.h>
#include <cstdint>

#define NN 524288   // nodes
#define DD 256      // input dim
#define HH 128      // hidden dim
#define BB 2048     // segments

// ---------------- scratch (device globals; no allocation allowed) ----------
__device__ float    g_scores[NN];
__device__ float    g_segmax[BB];
__device__ float    g_segsum[BB];
__device__ uint32_t g_w1p[DD * HH];   // permuted tf32(rna) W1: [k][(c&7)*16 + (c>>3)]

// ---------------- helpers ---------------------------------------------------
__device__ __forceinline__ uint32_t f2tf32(float f) {
    uint32_t u;
    asm("cvt.rna.tf32.f32 %0, %1;" : "=r"(u) : "f"(f));
    return u;
}
__device__ __forceinline__ float tanha(float x) {
    float y;
    asm("tanh.approx.f32 %0, %1;" : "=f"(y) : "f"(x));
    return y;
}
__device__ __forceinline__ uint32_t smem_u32(const void* p) {
    uint32_t a;
    asm("{ .reg .u64 t; cvta.to.shared.u64 t, %1; cvt.u32.u64 %0, t; }" : "=r"(a) : "l"(p));
    return a;
}
#define CP16(dst, src)  asm volatile("cp.async.ca.shared.global [%0], [%1], 16;" :: "r"(dst), "l"(src) : "memory")
#define CP_COMMIT()     asm volatile("cp.async.commit_group;" ::: "memory")
#define CP_WAIT(n)      asm volatile("cp.async.wait_group %0;" :: "n"(n) : "memory")

__device__ __forceinline__ void mma_tf32(float& c0, float& c1, float& c2, float& c3,
                                         uint32_t a0, uint32_t a1, uint32_t a2, uint32_t a3,
                                         uint32_t b0, uint32_t b1) {
    asm("mma.sync.aligned.m16n8k8.row.col.f32.tf32.tf32.f32 "
        "{%0,%1,%2,%3}, {%4,%5,%6,%7}, {%8,%9}, {%0,%1,%2,%3};"
        : "+f"(c0), "+f"(c1), "+f"(c2), "+f"(c3)
        : "r"(a0), "r"(a1), "r"(a2), "r"(a3), "r"(b0), "r"(b1));
}

// ---------------- kernel 0: permute + tf32-convert W1 (one-shot, tiny) -----
__global__ void w1perm_kernel(const float* __restrict__ W1) {
    int k = blockIdx.x;          // 0..255
    int c = threadIdx.x;         // 0..127
    g_w1p[k * HH + (c & 7) * 16 + (c >> 3)] = f2tf32(W1[k * HH + c]);
}

// ---------------- kernel A: scores = tanh(x@W1 + b1) @ W2 + b2 -------------
// 256 threads (8 warps), 1 CTA/SM. CTA tile: 256 nodes x 128 cols.
// Warp tile: 64 nodes x 64 cols (4 row-atoms x 8 col-atoms, 128 acc regs).
//   wid&3 = node slice (64 nodes), wid>>2 = column half.
// Both operands staged via cp.async (no staging regs / cvt / STS):
//   x chunk: row-major, node stride 36 words (conflict-free A-LDS: bank=4g+t).
//   W1 chunk: from pre-permuted g_w1p, row stride 132 (conflict-free LDS.128).
// x enters MMA as raw f32 bits (HW tf32 truncation); W1 is rna-converted.
#define KC 32
#define XS_STRIDE  36
#define W1P_STRIDE 132
#define XBUF_B  (256 * XS_STRIDE * 4)   // 36864 B
#define W1BUF_B (KC * W1P_STRIDE * 4)   // 16896 B
#define OFF_X    0
#define OFF_W1   (2 * XBUF_B)            // 73728
#define OFF_B1   (OFF_W1 + 2 * W1BUF_B)  // 107520
#define OFF_W2   (OFF_B1 + 512)
#define OFF_PART (OFF_W2 + 512)
#define OFF_B2   (OFF_PART + 1024)
#define SMEM_A_BYTES (OFF_B2 + 16)       // ~109.6 KB

__global__ void __launch_bounds__(256, 1)
scores_kernel(const float* __restrict__ x,
              const float* __restrict__ b1,
              const float* __restrict__ W2,
              const float* __restrict__ b2) {
    extern __shared__ char smem[];
    const uint32_t sb = smem_u32(smem);

    float* b1s  = (float*)(smem + OFF_B1);
    float* w2s  = (float*)(smem + OFF_W2);
    float* part = (float*)(smem + OFF_PART);   // 256 floats

    const int tid  = threadIdx.x;
    const int lane = tid & 31;
    const int wid  = tid >> 5;
    const int t    = lane & 3;          // k row within group
    const int g    = lane >> 2;         // group id
    const int wn   = (wid & 3) * 64;    // warp node base (64-node slice)
    const int chf  = wid >> 2;          // column half
    const int n0   = blockIdx.x * 256;

    if (tid < 128) { b1s[tid] = b1[tid]; w2s[tid] = W2[tid]; }
    if (tid == 0)  { ((float*)(smem + OFF_B2))[0] = b2[0]; }

    float acc[4][8][4];
    #pragma unroll
    for (int ra = 0; ra < 4; ++ra)
        #pragma unroll
        for (int j = 0; j < 8; ++j)
            #pragma unroll
            for (int r = 0; r < 4; ++r) acc[ra][j][r] = 0.0f;

    const char* xsrc = (const char*)x;
    const char* wsrc = (const char*)g_w1p;

    // per-thread staging decompositions (constant)
    const int xnode = tid >> 3, xq = tid & 7;   // +i*32 nodes, 16B group xq
    const int wrow  = tid >> 5, wq = tid & 31;  // +tt*8 k-rows, 16B group wq

    // ---- prologue: cp.async chunk 0 (x + W1) into buf 0 ----
    #pragma unroll
    for (int i = 0; i < 8; ++i) {
        int node = xnode + i * 32;
        CP16(sb + OFF_X + (uint32_t)(node * XS_STRIDE + 4 * xq) * 4,
             xsrc + ((size_t)(n0 + node) * DD + 4 * xq) * 4);
    }
    #pragma unroll
    for (int tt = 0; tt < 4; ++tt) {
        int row = wrow + tt * 8;
        CP16(sb + OFF_W1 + (uint32_t)(row * W1P_STRIDE + 4 * wq) * 4,
             wsrc + (size_t)(row * 128 + 4 * wq) * 4);
    }
    CP_COMMIT();

    for (int ch = 0; ch < 8; ++ch) {
        const int buf = ch & 1;
        uint32_t* xb  = (uint32_t*)(smem + OFF_X  + buf * XBUF_B);
        uint32_t* w1b = (uint32_t*)(smem + OFF_W1 + buf * W1BUF_B);

        // ---- issue next chunk's loads into the other buffer ----
        if (ch < 7) {
            const uint32_t xo = OFF_X  + (buf ^ 1) * XBUF_B;
            const uint32_t wo = OFF_W1 + (buf ^ 1) * W1BUF_B;
            #pragma unroll
            for (int i = 0; i < 8; ++i) {
                int node = xnode + i * 32;
                CP16(sb + xo + (uint32_t)(node * XS_STRIDE + 4 * xq) * 4,
                     xsrc + ((size_t)(n0 + node) * DD + (ch + 1) * KC + 4 * xq) * 4);
            }
            #pragma unroll
            for (int tt = 0; tt < 4; ++tt) {
                int row = wrow + tt * 8;
                CP16(sb + wo + (uint32_t)(row * W1P_STRIDE + 4 * wq) * 4,
                     wsrc + (size_t)(((ch + 1) * KC + row) * 128 + 4 * wq) * 4);
            }
            CP_COMMIT();
            CP_WAIT(1);    // chunk ch complete; ch+1 stays in flight
        } else {
            CP_WAIT(0);
        }
        __syncthreads();

        // ---- compute 4 k-steps ----
        #pragma unroll
        for (int ks = 0; ks < 4; ++ks) {
            const int kl = ks * 8;
            // A fragments: 8 node rows x 2 k positions (scalar LDS, bank=4g+t)
            uint32_t ax[8][2];
            #pragma unroll
            for (int m = 0; m < 8; ++m) {
                ax[m][0] = xb[(wn + g + 8 * m) * XS_STRIDE + kl + t];
                ax[m][1] = xb[(wn + g + 8 * m) * XS_STRIDE + kl + t + 4];
            }
            // B fragments: 8 col-atoms x 2 k positions (LDS.128, conflict-free)
            const uint32_t* r0 = w1b + (kl + t) * W1P_STRIDE + g * 16 + chf * 8;
            const uint32_t* r1 = r0 + 4 * W1P_STRIDE;
            uint4 u0 = *(const uint4*)(r0);
            uint4 u1 = *(const uint4*)(r0 + 4);
            uint4 v0 = *(const uint4*)(r1);
            uint4 v1 = *(const uint4*)(r1 + 4);
            uint32_t bu[8] = {u0.x, u0.y, u0.z, u0.w, u1.x, u1.y, u1.z, u1.w};
            uint32_t bv[8] = {v0.x, v0.y, v0.z, v0.w, v1.x, v1.y, v1.z, v1.w};

            #pragma unroll
            for (int ra = 0; ra < 4; ++ra) {
                uint32_t a0 = ax[2 * ra][0],  a1 = ax[2 * ra + 1][0];
                uint32_t a2 = ax[2 * ra][1],  a3 = ax[2 * ra + 1][1];
                #pragma unroll
                for (int j = 0; j < 8; ++j) {
                    mma_tf32(acc[ra][j][0], acc[ra][j][1], acc[ra][j][2], acc[ra][j][3],
                             a0, a1, a2, a3, bu[j], bv[j]);
                }
            }
        }
        __syncthreads();
    }

    // ---- epilogue: +b1, tanh, dot W2, reduce over t, combine col halves ----
    // p[2*ra]   -> node wn + 16*ra + g
    // p[2*ra+1] -> node wn + 16*ra + g + 8
    float p[8];
    #pragma unroll
    for (int i = 0; i < 8; ++i) p[i] = 0.0f;
    #pragma unroll
    for (int ra = 0; ra < 4; ++ra) {
        #pragma unroll
        for (int j = 0; j < 8; ++j) {
            #pragma unroll
            for (int rr = 0; rr < 2; ++rr) {
                int cc = (chf * 8 + j) * 8 + 2 * t + rr;
                float bb = b1s[cc], ww = w2s[cc];
                p[2 * ra]     += tanha(acc[ra][j][rr]     + bb) * ww;
                p[2 * ra + 1] += tanha(acc[ra][j][2 + rr] + bb) * ww;
            }
        }
    }
    #pragma unroll
    for (int i = 0; i < 8; ++i) {
        p[i] += __shfl_xor_sync(0xffffffffu, p[i], 1);
        p[i] += __shfl_xor_sync(0xffffffffu, p[i], 2);
    }
    if (t == 0 && chf == 0) {
        #pragma unroll
        for (int ra = 0; ra < 4; ++ra) {
            part[wn + 16 * ra + g]     = p[2 * ra];
            part[wn + 16 * ra + g + 8] = p[2 * ra + 1];
        }
    }
    __syncthreads();
    if (t == 0 && chf == 1) {
        float bb2 = ((float*)(smem + OFF_B2))[0];
        #pragma unroll
        for (int ra = 0; ra < 4; ++ra) {
            int node = wn + 16 * ra + g;
            g_scores[n0 + node]     = part[node]     + p[2 * ra]     + bb2;
            g_scores[n0 + node + 8] = part[node + 8] + p[2 * ra + 1] + bb2;
        }
    }
}

// ---------------- binary search ---------------------------------------------
__device__ __forceinline__ int lower_bound_i32(const int* __restrict__ a, int n, int v) {
    int lo = 0, hi = n;
    while (lo < hi) {
        int mid = (lo + hi) >> 1;
        if (a[mid] < v) lo = mid + 1; else hi = mid;
    }
    return lo;
}

// ---------------- kernel B: per-segment max + sum(exp) ----------------------
__global__ void segstats_kernel(const int* __restrict__ batch) {
    const int b = blockIdx.x;
    const int tid = threadIdx.x;
    __shared__ int se[2];
    __shared__ float red[256];

    if (tid == 0) {
        se[0] = lower_bound_i32(batch, NN, b);
        se[1] = lower_bound_i32(batch, NN, b + 1);
    }
    __syncthreads();
    const int st = se[0], en = se[1];

    float m = -1e30f;
    for (int i = st + tid; i < en; i += 256) m = fmaxf(m, g_scores[i]);
    red[tid] = m;
    __syncthreads();
    #pragma unroll
    for (int off = 128; off > 0; off >>= 1) {
        if (tid < off) red[tid] = fmaxf(red[tid], red[tid + off]);
        __syncthreads();
    }
    m = red[0];
    __syncthreads();

    float z = 0.0f;
    for (int i = st + tid; i < en; i += 256) z += expf(g_scores[i] - m);
    red[tid] = z;
    __syncthreads();
    #pragma unroll
    for (int off = 128; off > 0; off >>= 1) {
        if (tid < off) red[tid] += red[tid + off];
        __syncthreads();
    }
    if (tid == 0) {
        if (en > st) { g_segmax[b] = m; g_segsum[b] = red[0]; }
        else         { g_segmax[b] = 0.0f; g_segsum[b] = 0.0f; }
    }
}

// ---------------- kernel C: pooled[b,d] = sum_i x[i,d] * w_i (R5 version) ---
__global__ void pool_kernel(const float* __restrict__ x,
                            const int* __restrict__ batch,
                            float* __restrict__ out) {
    const int b = blockIdx.x;
    const int tid = threadIdx.x;   // = dim d (0..255)
    __shared__ int se[2];
    __shared__ float ws[256];

    if (tid == 0) {
        se[0] = lower_bound_i32(batch, NN, b);
        se[1] = lower_bound_i32(batch, NN, b + 1);
    }
    __syncthreads();
    const int st = se[0], en = se[1];
    const float m = g_segmax[b];
    const float Z = g_segsum[b];
    const float invZ = (en > st && Z > 0.0f) ? (1.0f / Z) : 0.0f;

    float acc = 0.0f;
    for (int i0 = st; i0 < en; i0 += 256) {
        int cnt = min(256, en - i0);
        __syncthreads();
        if (tid < cnt) ws[tid] = expf(g_scores[i0 + tid] - m) * invZ;
        __syncthreads();
        const float* xp = x + (size_t)i0 * DD + tid;
        int j = 0;
        for (; j + 8 <= cnt; j += 8) {
            float v0 = xp[(size_t)(j + 0) * DD];
            float v1 = xp[(size_t)(j + 1) * DD];
            float v2 = xp[(size_t)(j + 2) * DD];
            float v3 = xp[(size_t)(j + 3) * DD];
            float v4 = xp[(size_t)(j + 4) * DD];
            float v5 = xp[(size_t)(j + 5) * DD];
            float v6 = xp[(size_t)(j + 6) * DD];
            float v7 = xp[(size_t)(j + 7) * DD];
            acc += v0 * ws[j + 0]; acc += v1 * ws[j + 1];
            acc += v2 * ws[j + 2]; acc += v3 * ws[j + 3];
            acc += v4 * ws[j + 4]; acc += v5 * ws[j + 5];
            acc += v6 * ws[j + 6]; acc += v7 * ws[j + 7];
        }
        for (; j < cnt; ++j) acc += xp[(size_t)j * DD] * ws[j];
    }
    out[(size_t)b * DD + tid] = acc;
}

// ---------------- launch ------------------------------------------------------
extern "C" void kernel_launch(void* const* d_in, const int* in_sizes, int n_in,
                              void* d_out, int out_size) {
    (void)in_sizes; (void)n_in; (void)out_size;
    const float* x     = (const float*)d_in[0];
    const int*   batch = (const int*)d_in[1];
    const float* W1    = (const float*)d_in[2];
    const float* b1    = (const float*)d_in[3];
    const float* W2    = (const float*)d_in[4];
    const float* b2    = (const float*)d_in[5];
    float*       out   = (float*)d_out;

    cudaFuncSetAttribute(scores_kernel,
                         cudaFuncAttributeMaxDynamicSharedMemorySize,
                         SMEM_A_BYTES);

    w1perm_kernel<<<DD, HH>>>(W1);
    scores_kernel<<<NN / 256, 256, SMEM_A_BYTES>>>(x, b1, W2, b2);
    segstats_kernel<<<BB, 256>>>(batch);
    pool_kernel<<<BB, 256>>>(x, batch, out);
}

// round 9
// speedup vs baseline: 2.2189x; 1.0668x over previous
#include <cuda_runtime.h>
#include <cstdint>

#define NN 524288   // nodes
#define DD 256      // input dim
#define HH 128      // hidden dim
#define BB 2048     // segments

// ---------------- scratch (device globals; no allocation allowed) ----------
__device__ float    g_scores[NN];
__device__ float    g_wts[NN];        // unnormalized exp weights
__device__ float    g_segmax[BB];
__device__ float    g_segsum[BB];
__device__ uint32_t g_w1p[DD * HH];   // permuted tf32(rna) W1: [k][(c&7)*16 + (c>>3)]

// ---------------- helpers ---------------------------------------------------
__device__ __forceinline__ uint32_t f2tf32(float f) {
    uint32_t u;
    asm("cvt.rna.tf32.f32 %0, %1;" : "=r"(u) : "f"(f));
    return u;
}
__device__ __forceinline__ float tanha(float x) {
    float y;
    asm("tanh.approx.f32 %0, %1;" : "=f"(y) : "f"(x));
    return y;
}
__device__ __forceinline__ uint32_t smem_u32(const void* p) {
    uint32_t a;
    asm("{ .reg .u64 t; cvta.to.shared.u64 t, %1; cvt.u32.u64 %0, t; }" : "=r"(a) : "l"(p));
    return a;
}
#define CP16(dst, src)  asm volatile("cp.async.ca.shared.global [%0], [%1], 16;" :: "r"(dst), "l"(src) : "memory")
#define CP_COMMIT()     asm volatile("cp.async.commit_group;" ::: "memory")
#define CP_WAIT(n)      asm volatile("cp.async.wait_group %0;" :: "n"(n) : "memory")

__device__ __forceinline__ void mma_tf32(float& c0, float& c1, float& c2, float& c3,
                                         uint32_t a0, uint32_t a1, uint32_t a2, uint32_t a3,
                                         uint32_t b0, uint32_t b1) {
    asm("mma.sync.aligned.m16n8k8.row.col.f32.tf32.tf32.f32 "
        "{%0,%1,%2,%3}, {%4,%5,%6,%7}, {%8,%9}, {%0,%1,%2,%3};"
        : "+f"(c0), "+f"(c1), "+f"(c2), "+f"(c3)
        : "r"(a0), "r"(a1), "r"(a2), "r"(a3), "r"(b0), "r"(b1));
}

// ---------------- kernel 0: permute + tf32-convert W1 (one-shot, tiny) -----
__global__ void w1perm_kernel(const float* __restrict__ W1) {
    int k = blockIdx.x;          // 0..255
    int c = threadIdx.x;         // 0..127
    g_w1p[k * HH + (c & 7) * 16 + (c >> 3)] = f2tf32(W1[k * HH + c]);
}

// ---------------- kernel A: scores = tanh(x@W1 + b1) @ W2 + b2 -------------
// 256 threads (8 warps), 2 CTAs/SM (16 warps/SM). CTA tile: 128 nodes x 128.
// Warp tile: 32 nodes x 64 cols (2 row-atoms x 8 col-atoms, 64 acc regs).
//   wid&3 = node slice, wid>>2 = column half.
// BOTH operands staged via cp.async (no staging regs / cvt / STS):
//   x chunk: row-major raw f32 (HW tf32 truncation), node stride 36 words.
//   W1 chunk: from pre-permuted rna-tf32 g_w1p, row stride 132.
#define KC 32
#define XS_STRIDE  36
#define W1P_STRIDE 132
#define XBUF_B  (128 * XS_STRIDE * 4)   // 18432 B
#define W1BUF_B (KC * W1P_STRIDE * 4)   // 16896 B
#define OFF_X    0
#define OFF_W1   (2 * XBUF_B)            // 36864
#define OFF_B1   (OFF_W1 + 2 * W1BUF_B)  // 70656
#define OFF_W2   (OFF_B1 + 512)
#define OFF_PART (OFF_W2 + 512)
#define OFF_B2   (OFF_PART + 512)
#define SMEM_A_BYTES (OFF_B2 + 16)       // ~72.2 KB  (2 CTAs -> 144.4 KB/SM)

__global__ void __launch_bounds__(256, 2)
scores_kernel(const float* __restrict__ x,
              const float* __restrict__ b1,
              const float* __restrict__ W2,
              const float* __restrict__ b2) {
    extern __shared__ char smem[];
    const uint32_t sb = smem_u32(smem);

    float* b1s  = (float*)(smem + OFF_B1);
    float* w2s  = (float*)(smem + OFF_W2);
    float* part = (float*)(smem + OFF_PART);

    const int tid  = threadIdx.x;
    const int lane = tid & 31;
    const int wid  = tid >> 5;
    const int t    = lane & 3;          // k row within group
    const int g    = lane >> 2;         // group id
    const int wn   = (wid & 3) * 32;    // warp node base (32-node slice)
    const int chf  = wid >> 2;          // column half
    const int n0   = blockIdx.x * 128;

    if (tid < 128) { b1s[tid] = b1[tid]; w2s[tid] = W2[tid]; }
    if (tid == 0)  { ((float*)(smem + OFF_B2))[0] = b2[0]; }

    float acc[2][8][4];
    #pragma unroll
    for (int ra = 0; ra < 2; ++ra)
        #pragma unroll
        for (int j = 0; j < 8; ++j)
            #pragma unroll
            for (int r = 0; r < 4; ++r) acc[ra][j][r] = 0.0f;

    const char* xsrc = (const char*)x;
    const char* wsrc = (const char*)g_w1p;

    // per-thread staging decompositions (constant)
    const int xnode = tid >> 3, xq = tid & 7;   // +i*32 nodes, 16B group xq
    const int wrow  = tid >> 5, wq = tid & 31;  // +tt*8 k-rows, 16B group wq

    // ---- prologue: cp.async chunk 0 (x + W1) into buf 0 ----
    #pragma unroll
    for (int i = 0; i < 4; ++i) {
        int node = xnode + i * 32;
        CP16(sb + OFF_X + (uint32_t)(node * XS_STRIDE + 4 * xq) * 4,
             xsrc + ((size_t)(n0 + node) * DD + 4 * xq) * 4);
    }
    #pragma unroll
    for (int tt = 0; tt < 4; ++tt) {
        int row = wrow + tt * 8;
        CP16(sb + OFF_W1 + (uint32_t)(row * W1P_STRIDE + 4 * wq) * 4,
             wsrc + (size_t)(row * 128 + 4 * wq) * 4);
    }
    CP_COMMIT();

    for (int ch = 0; ch < 8; ++ch) {
        const int buf = ch & 1;
        uint32_t* xb  = (uint32_t*)(smem + OFF_X  + buf * XBUF_B);
        uint32_t* w1b = (uint32_t*)(smem + OFF_W1 + buf * W1BUF_B);

        // ---- issue next chunk's loads into the other buffer ----
        if (ch < 7) {
            const uint32_t xo = OFF_X  + (buf ^ 1) * XBUF_B;
            const uint32_t wo = OFF_W1 + (buf ^ 1) * W1BUF_B;
            #pragma unroll
            for (int i = 0; i < 4; ++i) {
                int node = xnode + i * 32;
                CP16(sb + xo + (uint32_t)(node * XS_STRIDE + 4 * xq) * 4,
                     xsrc + ((size_t)(n0 + node) * DD + (ch + 1) * KC + 4 * xq) * 4);
            }
            #pragma unroll
            for (int tt = 0; tt < 4; ++tt) {
                int row = wrow + tt * 8;
                CP16(sb + wo + (uint32_t)(row * W1P_STRIDE + 4 * wq) * 4,
                     wsrc + (size_t)(((ch + 1) * KC + row) * 128 + 4 * wq) * 4);
            }
            CP_COMMIT();
            CP_WAIT(1);    // chunk ch complete; ch+1 stays in flight
        } else {
            CP_WAIT(0);
        }
        __syncthreads();

        // ---- compute 4 k-steps ----
        #pragma unroll
        for (int ks = 0; ks < 4; ++ks) {
            const int kl = ks * 8;
            // A fragments: 4 node rows x 2 k positions (scalar LDS, bank=4g+t)
            uint32_t ax[4][2];
            #pragma unroll
            for (int m = 0; m < 4; ++m) {
                ax[m][0] = xb[(wn + g + 8 * m) * XS_STRIDE + kl + t];
                ax[m][1] = xb[(wn + g + 8 * m) * XS_STRIDE + kl + t + 4];
            }
            // B fragments: 8 col-atoms x 2 k positions (LDS.128, conflict-free)
            const uint32_t* r0 = w1b + (kl + t) * W1P_STRIDE + g * 16 + chf * 8;
            const uint32_t* r1 = r0 + 4 * W1P_STRIDE;
            uint4 u0 = *(const uint4*)(r0);
            uint4 u1 = *(const uint4*)(r0 + 4);
            uint4 v0 = *(const uint4*)(r1);
            uint4 v1 = *(const uint4*)(r1 + 4);
            uint32_t bu[8] = {u0.x, u0.y, u0.z, u0.w, u1.x, u1.y, u1.z, u1.w};
            uint32_t bv[8] = {v0.x, v0.y, v0.z, v0.w, v1.x, v1.y, v1.z, v1.w};

            #pragma unroll
            for (int ra = 0; ra < 2; ++ra) {
                uint32_t a0 = ax[2 * ra][0],  a1 = ax[2 * ra + 1][0];
                uint32_t a2 = ax[2 * ra][1],  a3 = ax[2 * ra + 1][1];
                #pragma unroll
                for (int j = 0; j < 8; ++j) {
                    mma_tf32(acc[ra][j][0], acc[ra][j][1], acc[ra][j][2], acc[ra][j][3],
                             a0, a1, a2, a3, bu[j], bv[j]);
                }
            }
        }
        __syncthreads();
    }

    // ---- epilogue: +b1, tanh, dot W2, reduce over t, combine col halves ----
    float p[4] = {0.f, 0.f, 0.f, 0.f};
    #pragma unroll
    for (int ra = 0; ra < 2; ++ra) {
        #pragma unroll
        for (int j = 0; j < 8; ++j) {
            #pragma unroll
            for (int rr = 0; rr < 2; ++rr) {
                int cc = (chf * 8 + j) * 8 + 2 * t + rr;
                float bb = b1s[cc], ww = w2s[cc];
                p[2 * ra]     += tanha(acc[ra][j][rr]     + bb) * ww;
                p[2 * ra + 1] += tanha(acc[ra][j][2 + rr] + bb) * ww;
            }
        }
    }
    #pragma unroll
    for (int i = 0; i < 4; ++i) {
        p[i] += __shfl_xor_sync(0xffffffffu, p[i], 1);
        p[i] += __shfl_xor_sync(0xffffffffu, p[i], 2);
    }
    if (t == 0 && chf == 0) {
        part[wn + g]      = p[0];
        part[wn + g + 8]  = p[1];
        part[wn + g + 16] = p[2];
        part[wn + g + 24] = p[3];
    }
    __syncthreads();
    if (t == 0 && chf == 1) {
        float bb2 = ((float*)(smem + OFF_B2))[0];
        g_scores[n0 + wn + g]      = part[wn + g]      + p[0] + bb2;
        g_scores[n0 + wn + g + 8]  = part[wn + g + 8]  + p[1] + bb2;
        g_scores[n0 + wn + g + 16] = part[wn + g + 16] + p[2] + bb2;
        g_scores[n0 + wn + g + 24] = part[wn + g + 24] + p[3] + bb2;
    }
}

// ---------------- binary search ---------------------------------------------
__device__ __forceinline__ int lower_bound_i32(const int* __restrict__ a, int n, int v) {
    int lo = 0, hi = n;
    while (lo < hi) {
        int mid = (lo + hi) >> 1;
        if (a[mid] < v) lo = mid + 1; else hi = mid;
    }
    return lo;
}

// ---------------- kernel B: per-segment max + sum(exp) + exp weights --------
__global__ void segstats_kernel(const int* __restrict__ batch) {
    const int b = blockIdx.x;
    const int tid = threadIdx.x;
    __shared__ int se[2];
    __shared__ float red[256];

    if (tid == 0) {
        se[0] = lower_bound_i32(batch, NN, b);
        se[1] = lower_bound_i32(batch, NN, b + 1);
    }
    __syncthreads();
    const int st = se[0], en = se[1];

    float m = -1e30f;
    for (int i = st + tid; i < en; i += 256) m = fmaxf(m, g_scores[i]);
    red[tid] = m;
    __syncthreads();
    #pragma unroll
    for (int off = 128; off > 0; off >>= 1) {
        if (tid < off) red[tid] = fmaxf(red[tid], red[tid + off]);
        __syncthreads();
    }
    m = red[0];
    __syncthreads();

    float z = 0.0f;
    for (int i = st + tid; i < en; i += 256) {
        float e = expf(g_scores[i] - m);
        g_wts[i] = e;         // store unnormalized weight
        z += e;
    }
    red[tid] = z;
    __syncthreads();
    #pragma unroll
    for (int off = 128; off > 0; off >>= 1) {
        if (tid < off) red[tid] += red[tid + off];
        __syncthreads();
    }
    if (tid == 0) {
        g_segsum[b] = (en > st) ? red[0] : 0.0f;
    }
}

// ---------------- kernel C: pooled[b,d] = invZ * sum_i x[i,d] * e_i ---------
// 256 threads = dims; pure streaming, no barriers in the loop.
__global__ void pool_kernel(const float* __restrict__ x,
                            const int* __restrict__ batch,
                            float* __restrict__ out) {
    const int b = blockIdx.x;
    const int tid = threadIdx.x;   // dim d
    __shared__ int se[2];

    if (tid == 0) {
        se[0] = lower_bound_i32(batch, NN, b);
        se[1] = lower_bound_i32(batch, NN, b + 1);
    }
    __syncthreads();
    const int st = se[0], en = se[1];
    const float Z = g_segsum[b];
    const float invZ = (en > st && Z > 0.0f) ? (1.0f / Z) : 0.0f;

    const float* xp = x + (size_t)st * DD + tid;
    const float* wp = g_wts + st;
    const int n = en - st;

    float acc = 0.0f;
    int j = 0;
    for (; j + 8 <= n; j += 8) {
        float v0 = xp[(size_t)(j + 0) * DD];
        float v1 = xp[(size_t)(j + 1) * DD];
        float v2 = xp[(size_t)(j + 2) * DD];
        float v3 = xp[(size_t)(j + 3) * DD];
        float v4 = xp[(size_t)(j + 4) * DD];
        float v5 = xp[(size_t)(j + 5) * DD];
        float v6 = xp[(size_t)(j + 6) * DD];
        float v7 = xp[(size_t)(j + 7) * DD];
        float w0 = __ldg(wp + j + 0), w1 = __ldg(wp + j + 1);
        float w2 = __ldg(wp + j + 2), w3 = __ldg(wp + j + 3);
        float w4 = __ldg(wp + j + 4), w5 = __ldg(wp + j + 5);
        float w6 = __ldg(wp + j + 6), w7 = __ldg(wp + j + 7);
        acc += v0 * w0; acc += v1 * w1; acc += v2 * w2; acc += v3 * w3;
        acc += v4 * w4; acc += v5 * w5; acc += v6 * w6; acc += v7 * w7;
    }
    for (; j < n; ++j) acc += xp[(size_t)j * DD] * __ldg(wp + j);

    out[(size_t)b * DD + tid] = acc * invZ;
}

// ---------------- launch ------------------------------------------------------
extern "C" void kernel_launch(void* const* d_in, const int* in_sizes, int n_in,
                              void* d_out, int out_size) {
    (void)in_sizes; (void)n_in; (void)out_size;
    const float* x     = (const float*)d_in[0];
    const int*   batch = (const int*)d_in[1];
    const float* W1    = (const float*)d_in[2];
    const float* b1    = (const float*)d_in[3];
    const float* W2    = (const float*)d_in[4];
    const float* b2    = (const float*)d_in[5];
    float*       out   = (float*)d_out;

    cudaFuncSetAttribute(scores_kernel,
                         cudaFuncAttributeMaxDynamicSharedMemorySize,
                         SMEM_A_BYTES);

    w1perm_kernel<<<DD, HH>>>(W1);
    scores_kernel<<<NN / 128, 256, SMEM_A_BYTES>>>(x, b1, W2, b2);
    segstats_kernel<<<BB, 256>>>(batch);
    pool_kernel<<<BB, 256>>>(x, batch, out);
}

// round 10
// speedup vs baseline: 2.5962x; 1.1700x over previous
#include <cuda_runtime.h>
#include <cuda_fp16.h>
#include <cstdint>

#define NN 524288   // nodes
#define DD 256      // input dim
#define HH 128      // hidden dim
#define BB 2048     // segments

// ---------------- scratch (device globals; no allocation allowed) ----------
__device__ float    g_scores[NN];
__device__ float    g_wts[NN];          // unnormalized exp weights
__device__ float    g_segsum[BB];
__device__ uint32_t g_w1ph[(DD / 2) * HH];  // permuted half2 W1: [k2][(c&7)*16+(c>>3)]
                                            // half2 = (W1[2k2][c], W1[2k2+1][c])

// ---------------- helpers ---------------------------------------------------
__device__ __forceinline__ float tanha(float x) {
    float y;
    asm("tanh.approx.f32 %0, %1;" : "=f"(y) : "f"(x));
    return y;
}
__device__ __forceinline__ uint32_t smem_u32(const void* p) {
    uint32_t a;
    asm("{ .reg .u64 t; cvta.to.shared.u64 t, %1; cvt.u32.u64 %0, t; }" : "=r"(a) : "l"(p));
    return a;
}
__device__ __forceinline__ uint32_t pack_h2(float lo, float hi) {
    __half2 h = __floats2half2_rn(lo, hi);
    return *(uint32_t*)&h;
}
#define CP16(dst, src)  asm volatile("cp.async.ca.shared.global [%0], [%1], 16;" :: "r"(dst), "l"(src) : "memory")
#define CP_COMMIT()     asm volatile("cp.async.commit_group;" ::: "memory")
#define CP_WAIT(n)      asm volatile("cp.async.wait_group %0;" :: "n"(n) : "memory")

__device__ __forceinline__ void mma_f16(float& c0, float& c1, float& c2, float& c3,
                                        uint32_t a0, uint32_t a1, uint32_t a2, uint32_t a3,
                                        uint32_t b0, uint32_t b1) {
    asm("mma.sync.aligned.m16n8k16.row.col.f32.f16.f16.f32 "
        "{%0,%1,%2,%3}, {%4,%5,%6,%7}, {%8,%9}, {%0,%1,%2,%3};"
        : "+f"(c0), "+f"(c1), "+f"(c2), "+f"(c3)
        : "r"(a0), "r"(a1), "r"(a2), "r"(a3), "r"(b0), "r"(b1));
}

// ---------------- kernel 0: W1 -> permuted packed half2 (one-shot) ---------
// Column c = a*8 + gg maps to gg*16 + a; half2 packs k pair (2k2, 2k2+1).
__global__ void w1h_kernel(const float* __restrict__ W1) {
    int k2 = blockIdx.x;         // 0..127
    int c  = threadIdx.x;        // 0..127
    g_w1ph[k2 * HH + (c & 7) * 16 + (c >> 3)] =
        pack_h2(W1[(2 * k2) * HH + c], W1[(2 * k2 + 1) * HH + c]);
}

// ---------------- kernel A: scores = tanh(x@W1 + b1) @ W2 + b2 -------------
// fp16 m16n8k16. 256 threads (8 warps), 2 CTAs/SM. CTA tile: 128 nodes x 128.
// Warp tile: 32 nodes x 64 cols (2 row-atoms x 8 col-atoms).
//   wid&3 = node slice, wid>>2 = column half.
// x: f32 LDG -> cvt half2 -> STS; smem layout [node][k2], stride 20 words
//    (conflict-free for all A-fragment LDS; stores have a benign 2-way).
// W1: cp.async from pre-permuted g_w1ph, row stride 132 words (conflict-free
//     LDS.128 B-frags). Both double-buffered.
#define KC 32
#define K2C 16
#define XS_STRIDE  20
#define W1P_STRIDE 132
#define XBUF_B  (128 * XS_STRIDE * 4)   // 10240 B
#define W1BUF_B (K2C * W1P_STRIDE * 4)  // 8448 B
#define OFF_X    0
#define OFF_W1   (2 * XBUF_B)            // 20480
#define OFF_B1   (OFF_W1 + 2 * W1BUF_B)  // 37376
#define OFF_W2   (OFF_B1 + 512)
#define OFF_PART (OFF_W2 + 512)
#define OFF_B2   (OFF_PART + 512)
#define SMEM_A_BYTES (OFF_B2 + 16)       // ~38.9 KB (2 CTAs -> ~78 KB/SM)

__global__ void __launch_bounds__(256, 2)
scores_kernel(const float* __restrict__ x,
              const float* __restrict__ b1,
              const float* __restrict__ W2,
              const float* __restrict__ b2) {
    extern __shared__ char smem[];
    const uint32_t sb = smem_u32(smem);

    float* b1s  = (float*)(smem + OFF_B1);
    float* w2s  = (float*)(smem + OFF_W2);
    float* part = (float*)(smem + OFF_PART);

    const int tid  = threadIdx.x;
    const int lane = tid & 31;
    const int wid  = tid >> 5;
    const int t    = lane & 3;          // k2 row within group
    const int g    = lane >> 2;         // group id
    const int wn   = (wid & 3) * 32;    // warp node base
    const int chf  = wid >> 2;          // column half
    const int n0   = blockIdx.x * 128;

    if (tid < 128) { b1s[tid] = b1[tid]; w2s[tid] = W2[tid]; }
    if (tid == 0)  { ((float*)(smem + OFF_B2))[0] = b2[0]; }

    float acc[2][8][4];
    #pragma unroll
    for (int ra = 0; ra < 2; ++ra)
        #pragma unroll
        for (int j = 0; j < 8; ++j)
            #pragma unroll
            for (int r = 0; r < 4; ++r) acc[ra][j][r] = 0.0f;

    const float4* x4   = (const float4*)x;
    const char*   wsrc = (const char*)g_w1ph;

    // staging decompositions
    const int xnode = tid >> 1, xjj = tid & 1;  // x: node, j' = xjj + 2i
    const int wrow  = tid >> 5, wq  = tid & 31; // W1: +tt*8 k2-rows, 16B group

    // ---- prologue: cp.async W1 chunk 0; prefetch x chunk 0 ----
    #pragma unroll
    for (int tt = 0; tt < 2; ++tt) {
        int row = wrow + tt * 8;
        CP16(sb + OFF_W1 + (uint32_t)(row * W1P_STRIDE + 4 * wq) * 4,
             wsrc + (size_t)(row * HH + 4 * wq) * 4);
    }
    CP_COMMIT();

    float4 rx[4];   // [i][pair]: i in 0..1, two float4 each
    #pragma unroll
    for (int i = 0; i < 2; ++i) {
        int jp = xjj + 2 * i;
        rx[2 * i]     = x4[(size_t)(n0 + xnode) * 64 + 2 * jp];
        rx[2 * i + 1] = x4[(size_t)(n0 + xnode) * 64 + 2 * jp + 1];
    }

    for (int ch = 0; ch < 8; ++ch) {
        const int buf = ch & 1;
        uint32_t* xb  = (uint32_t*)(smem + OFF_X  + buf * XBUF_B);
        uint32_t* w1b = (uint32_t*)(smem + OFF_W1 + buf * W1BUF_B);

        // ---- store staged x chunk (cvt to half2, STS.128) ----
        #pragma unroll
        for (int i = 0; i < 2; ++i) {
            int jp = xjj + 2 * i;
            float4 f0 = rx[2 * i], f1 = rx[2 * i + 1];
            uint4 u;
            u.x = pack_h2(f0.x, f0.y); u.y = pack_h2(f0.z, f0.w);
            u.z = pack_h2(f1.x, f1.y); u.w = pack_h2(f1.z, f1.w);
            *(uint4*)(xb + xnode * XS_STRIDE + 4 * jp) = u;
        }

        // ---- issue next chunk's loads ----
        if (ch < 7) {
            const uint32_t wo = OFF_W1 + (buf ^ 1) * W1BUF_B;
            #pragma unroll
            for (int tt = 0; tt < 2; ++tt) {
                int row = wrow + tt * 8;
                CP16(sb + wo + (uint32_t)(row * W1P_STRIDE + 4 * wq) * 4,
                     wsrc + (size_t)(((ch + 1) * K2C + row) * HH + 4 * wq) * 4);
            }
            CP_COMMIT();
            #pragma unroll
            for (int i = 0; i < 2; ++i) {
                int jp = xjj + 2 * i;
                rx[2 * i]     = x4[(size_t)(n0 + xnode) * 64 + (ch + 1) * 8 + 2 * jp];
                rx[2 * i + 1] = x4[(size_t)(n0 + xnode) * 64 + (ch + 1) * 8 + 2 * jp + 1];
            }
            CP_WAIT(1);   // chunk ch's W1 complete; ch+1 in flight
        } else {
            CP_WAIT(0);
        }
        __syncthreads();

        // ---- compute 2 k-steps (K=16 each) ----
        #pragma unroll
        for (int ks = 0; ks < 2; ++ks) {
            const int k2l = ks * 8;
            // A fragments: 2 row-atoms x 4 regs (scalar LDS, conflict-free)
            uint32_t ax[2][4];
            #pragma unroll
            for (int ra = 0; ra < 2; ++ra) {
                const uint32_t* xr = xb + (wn + 16 * ra + g) * XS_STRIDE + k2l;
                ax[ra][0] = xr[t];
                ax[ra][1] = xr[8 * XS_STRIDE + t];        // row +8
                ax[ra][2] = xr[t + 4];
                ax[ra][3] = xr[8 * XS_STRIDE + t + 4];
            }
            // B fragments: 8 col-atoms x (b0,b1) via 4 LDS.128 (conflict-free)
            const uint32_t* r0 = w1b + (k2l + t) * W1P_STRIDE + g * 16 + chf * 8;
            const uint32_t* r1 = r0 + 4 * W1P_STRIDE;
            uint4 u0 = *(const uint4*)(r0);
            uint4 u1 = *(const uint4*)(r0 + 4);
            uint4 v0 = *(const uint4*)(r1);
            uint4 v1 = *(const uint4*)(r1 + 4);
            uint32_t bu[8] = {u0.x, u0.y, u0.z, u0.w, u1.x, u1.y, u1.z, u1.w};
            uint32_t bv[8] = {v0.x, v0.y, v0.z, v0.w, v1.x, v1.y, v1.z, v1.w};

            #pragma unroll
            for (int ra = 0; ra < 2; ++ra) {
                #pragma unroll
                for (int j = 0; j < 8; ++j) {
                    mma_f16(acc[ra][j][0], acc[ra][j][1], acc[ra][j][2], acc[ra][j][3],
                            ax[ra][0], ax[ra][1], ax[ra][2], ax[ra][3],
                            bu[j], bv[j]);
                }
            }
        }
        __syncthreads();
    }

    // ---- epilogue: +b1, tanh, dot W2, reduce over t, combine col halves ----
    // p[2*ra] -> node wn+16ra+g ; p[2*ra+1] -> node wn+16ra+g+8
    float p[4] = {0.f, 0.f, 0.f, 0.f};
    #pragma unroll
    for (int ra = 0; ra < 2; ++ra) {
        #pragma unroll
        for (int j = 0; j < 8; ++j) {
            #pragma unroll
            for (int rr = 0; rr < 2; ++rr) {
                int cc = (chf * 8 + j) * 8 + 2 * t + rr;
                float bb = b1s[cc], ww = w2s[cc];
                p[2 * ra]     += tanha(acc[ra][j][rr]     + bb) * ww;
                p[2 * ra + 1] += tanha(acc[ra][j][2 + rr] + bb) * ww;
            }
        }
    }
    #pragma unroll
    for (int i = 0; i < 4; ++i) {
        p[i] += __shfl_xor_sync(0xffffffffu, p[i], 1);
        p[i] += __shfl_xor_sync(0xffffffffu, p[i], 2);
    }
    if (t == 0 && chf == 0) {
        part[wn + g]      = p[0];
        part[wn + g + 8]  = p[1];
        part[wn + g + 16] = p[2];
        part[wn + g + 24] = p[3];
    }
    __syncthreads();
    if (t == 0 && chf == 1) {
        float bb2 = ((float*)(smem + OFF_B2))[0];
        g_scores[n0 + wn + g]      = part[wn + g]      + p[0] + bb2;
        g_scores[n0 + wn + g + 8]  = part[wn + g + 8]  + p[1] + bb2;
        g_scores[n0 + wn + g + 16] = part[wn + g + 16] + p[2] + bb2;
        g_scores[n0 + wn + g + 24] = part[wn + g + 24] + p[3] + bb2;
    }
}

// ---------------- binary search ---------------------------------------------
__device__ __forceinline__ int lower_bound_i32(const int* __restrict__ a, int n, int v) {
    int lo = 0, hi = n;
    while (lo < hi) {
        int mid = (lo + hi) >> 1;
        if (a[mid] < v) lo = mid + 1; else hi = mid;
    }
    return lo;
}

// ---------------- kernel B: per-segment max + exp weights + sum -------------
__global__ void segstats_kernel(const int* __restrict__ batch) {
    const int b = blockIdx.x;
    const int tid = threadIdx.x;
    __shared__ int se[2];
    __shared__ float red[256];

    if (tid == 0) {
        se[0] = lower_bound_i32(batch, NN, b);
        se[1] = lower_bound_i32(batch, NN, b + 1);
    }
    __syncthreads();
    const int st = se[0], en = se[1];

    float m = -1e30f;
    for (int i = st + tid; i < en; i += 256) m = fmaxf(m, g_scores[i]);
    red[tid] = m;
    __syncthreads();
    #pragma unroll
    for (int off = 128; off > 0; off >>= 1) {
        if (tid < off) red[tid] = fmaxf(red[tid], red[tid + off]);
        __syncthreads();
    }
    m = red[0];
    __syncthreads();

    float z = 0.0f;
    for (int i = st + tid; i < en; i += 256) {
        float e = expf(g_scores[i] - m);
        g_wts[i] = e;
        z += e;
    }
    red[tid] = z;
    __syncthreads();
    #pragma unroll
    for (int off = 128; off > 0; off >>= 1) {
        if (tid < off) red[tid] += red[tid + off];
        __syncthreads();
    }
    if (tid == 0) g_segsum[b] = (en > st) ? red[0] : 0.0f;
}

// ---------------- kernel C: pooled[b,d] = sum_i x[i,d] * w_i (R5 form) ------
__global__ void pool_kernel(const float* __restrict__ x,
                            const int* __restrict__ batch,
                            float* __restrict__ out) {
    const int b = blockIdx.x;
    const int tid = threadIdx.x;   // dim d
    __shared__ int se[2];
    __shared__ float ws[256];

    if (tid == 0) {
        se[0] = lower_bound_i32(batch, NN, b);
        se[1] = lower_bound_i32(batch, NN, b + 1);
    }
    __syncthreads();
    const int st = se[0], en = se[1];
    const float Z = g_segsum[b];
    const float invZ = (en > st && Z > 0.0f) ? (1.0f / Z) : 0.0f;

    float acc = 0.0f;
    for (int i0 = st; i0 < en; i0 += 256) {
        int cnt = min(256, en - i0);
        __syncthreads();
        if (tid < cnt) ws[tid] = g_wts[i0 + tid] * invZ;
        __syncthreads();
        const float* xp = x + (size_t)i0 * DD + tid;
        int j = 0;
        for (; j + 8 <= cnt; j += 8) {
            float v0 = xp[(size_t)(j + 0) * DD];
            float v1 = xp[(size_t)(j + 1) * DD];
            float v2 = xp[(size_t)(j + 2) * DD];
            float v3 = xp[(size_t)(j + 3) * DD];
            float v4 = xp[(size_t)(j + 4) * DD];
            float v5 = xp[(size_t)(j + 5) * DD];
            float v6 = xp[(size_t)(j + 6) * DD];
            float v7 = xp[(size_t)(j + 7) * DD];
            acc += v0 * ws[j + 0]; acc += v1 * ws[j + 1];
            acc += v2 * ws[j + 2]; acc += v3 * ws[j + 3];
            acc += v4 * ws[j + 4]; acc += v5 * ws[j + 5];
            acc += v6 * ws[j + 6]; acc += v7 * ws[j + 7];
        }
        for (; j < cnt; ++j) acc += xp[(size_t)j * DD] * ws[j];
    }
    out[(size_t)b * DD + tid] = acc;
}

// ---------------- launch ------------------------------------------------------
extern "C" void kernel_launch(void* const* d_in, const int* in_sizes, int n_in,
                              void* d_out, int out_size) {
    (void)in_sizes; (void)n_in; (void)out_size;
    const float* x     = (const float*)d_in[0];
    const int*   batch = (const int*)d_in[1];
    const float* W1    = (const float*)d_in[2];
    const float* b1    = (const float*)d_in[3];
    const float* W2    = (const float*)d_in[4];
    const float* b2    = (const float*)d_in[5];
    float*       out   = (float*)d_out;

    cudaFuncSetAttribute(scores_kernel,
                         cudaFuncAttributeMaxDynamicSharedMemorySize,
                         SMEM_A_BYTES);

    w1h_kernel<<<DD / 2, HH>>>(W1);
    scores_kernel<<<NN / 128, 256, SMEM_A_BYTES>>>(x, b1, W2, b2);
    segstats_kernel<<<BB, 256>>>(batch);
    pool_kernel<<<BB, 256>>>(x, batch, out);
}